// round 16
// baseline (speedup 1.0000x reference)
#include <cuda_runtime.h>
#include <cuda_bf16.h>
#include <cstdint>

#define N      4096
#define D      64
#define NB     256      // 2 persistent blocks per SM, all co-resident
#define NTHR   256      // 8 warps
#define ITERS  100
#define NT     32       // 32 row-slabs
#define NHT    64       // 64 column half-tiles (64 cols each)
#define SA     36       // A bf16 smem row stride (uint32)

// ---------------- device globals (no allocation allowed) --------------------------
__device__ float    g_K[(size_t)N * N];   // written only for flagged half-tiles
__device__ float    g_M[(size_t)N * N];
__device__ float    g_u[N], g_v[N];
__device__ unsigned g_bar_count;
__device__ unsigned g_bar_phase;          // monotone across replays; compared relatively
__device__ int      g_changed[ITERS];
__device__ float    g_cost;
__device__ int      g_map2[NT * NHT];     // per 128x64 half-tile flag
__device__ int      g_blockany[NB];

// ---------------- grid barrier: arrivals atomic, polls are acquire LOADS -----------
__device__ __forceinline__ void gsync() {
    __syncthreads();
    if (threadIdx.x == 0) {
        __threadfence();
        unsigned ph = atomicAdd(&g_bar_phase, 0u);   // strong read BEFORE arrival
        if (atomicAdd(&g_bar_count, 1u) == (unsigned)NB - 1u) {
            atomicExch(&g_bar_count, 0u);
            atomicAdd(&g_bar_phase, 1u);             // release
        } else {
            unsigned cur;
            do {
                __nanosleep(64);
                asm volatile("ld.acquire.gpu.global.u32 %0, [%1];"
                             : "=r"(cur) : "l"(&g_bar_phase));
            } while (cur == ph);
        }
        __threadfence();
    }
    __syncthreads();
}

#define HMMA(accq, a0, a1, a2, a3, b0, b1)                                   \
    asm volatile(                                                            \
        "mma.sync.aligned.m16n8k16.row.col.f32.bf16.bf16.f32 "               \
        "{%0,%1,%2,%3}, {%4,%5,%6,%7}, {%8,%9}, {%0,%1,%2,%3};"              \
        : "+f"((accq)[0]), "+f"((accq)[1]), "+f"((accq)[2]), "+f"((accq)[3]) \
        : "r"(a0), "r"(a1), "r"(a2), "r"(a3), "r"(b0), "r"(b1))

// =============== the whole pipeline in ONE persistent kernel =======================
__global__ void __launch_bounds__(NTHR, 2) kern_all(const float* __restrict__ x0,
                                                    const float* __restrict__ x1,
                                                    float* __restrict__ out) {
    // u32 pool: Ah[4608] | sq1c[512] | sqA32[128] | sqA64[128] | mins1t[8] | flags[64]
    __shared__ uint32_t s_pool[5456];                // 21.8 KB
    uint32_t* const Ah     = s_pool;
    float*    const sq1c   = (float*)(s_pool + 4608);   // block-local col norms (dims 0..31)
    float*    const sqA32  = (float*)(s_pool + 5120);
    float*    const sqA64  = (float*)(s_pool + 5248);
    float*    const mins1t = (float*)(s_pool + 5376);   // per-half-tile min of sq1c
    int*      const flags  = (int*)(s_pool + 5384);     // [tile][warp] 8x8
    float*    const sred   = (float*)s_pool;            // phase-2 overlay

    const int tid  = threadIdx.x;
    const int bid  = blockIdx.x;
    const int lane = tid & 31;
    const int w    = tid >> 5;                // 0..7
    const int gid  = lane >> 2;
    const int pid  = lane & 3;
    const int wm   = w >> 1;                  // 0..3 (32-row strips)
    const int wn2  = w & 1;                   // 0..1 (32-col strips in 64)

    if (bid == 0) {
        if (tid == 0) g_cost = 0.0f;
        if (tid < ITERS) g_changed[tid] = 0;
    }

    const int rs  = bid >> 3;                 // row slab 0..31
    const int cg8 = bid & 7;                  // column group: cols cg8*512..+512

    // ---- block-local col norms (dims 0..31): 2 cols per thread ----
    {
        int c0 = 2 * tid;
        const float* xa = x1 + (size_t)(cg8 * 512 + c0) * D;
        const float* xb = xa + D;
        float sa = 0.0f, sb = 0.0f;
#pragma unroll
        for (int j = 0; j < 8; j++) {
            float4 ta = *(const float4*)(xa + j * 4);
            float4 tb = *(const float4*)(xb + j * 4);
            sa += ta.x * ta.x + ta.y * ta.y + ta.z * ta.z + ta.w * ta.w;
            sb += tb.x * tb.x + tb.y * tb.y + tb.z * tb.z + tb.w * tb.w;
        }
        sq1c[c0] = sa; sq1c[c0 + 1] = sb;
    }

    // ---- A slab: fp32 -> bf16 smem + in-pass row norms (4-shfl tree) ----
    {
        const float* GA = x0 + (size_t)(rs * 128) * D;
        const int q = tid & 15;
#pragma unroll
        for (int i = 0; i < 8; i++) {
            int f = tid + i * NTHR;           // 0..2047
            int r = f >> 4;
            float4 v = *(const float4*)(GA + (size_t)r * D + q * 4);
            __nv_bfloat162 p0 = __floats2bfloat162_rn(v.x, v.y);
            __nv_bfloat162 p1 = __floats2bfloat162_rn(v.z, v.w);
            Ah[r * SA + q * 2]     = *(uint32_t*)&p0;
            Ah[r * SA + q * 2 + 1] = *(uint32_t*)&p1;
            float s = v.x * v.x + v.y * v.y + v.z * v.z + v.w * v.w;
            s += __shfl_xor_sync(0xffffffffu, s, 1);
            s += __shfl_xor_sync(0xffffffffu, s, 2);
            s += __shfl_xor_sync(0xffffffffu, s, 4);   // 8-lane half sum
            float s64 = s + __shfl_xor_sync(0xffffffffu, s, 8);
            if (q == 0) { sqA32[r] = s; sqA64[r] = s64; }
        }
    }
    __syncthreads();   // Ah, sqA*, sq1c visible

    // ---- per-half-tile min of sq1c (warp w -> half-tile w) ----
    {
        float v = fminf(sq1c[w * 64 + lane], sq1c[w * 64 + 32 + lane]);
#pragma unroll
        for (int o = 16; o; o >>= 1) v = fminf(v, __shfl_xor_sync(0xffffffffu, v, o));
        if (lane == 0) mins1t[w] = v;
    }

    // ---- hoist A fragments (dims 0..31) + warp row-norm min ----
    const int AR = wm * 32;
    const int gr = rs * 128 + AR;
    uint32_t afr[2][2][4];
#pragma unroll
    for (int kk = 0; kk < 2; kk++) {
        const int ac = kk * 8 + pid;
#pragma unroll
        for (int mi = 0; mi < 2; mi++) {
            int r = AR + mi * 16 + gid;
            afr[kk][mi][0] = Ah[r * SA + ac];
            afr[kk][mi][1] = Ah[(r + 8) * SA + ac];
            afr[kk][mi][2] = Ah[r * SA + ac + 4];
            afr[kk][mi][3] = Ah[(r + 8) * SA + ac + 4];
        }
    }
    float r032[2][2];
#pragma unroll
    for (int mi = 0; mi < 2; mi++) {
        r032[mi][0] = sqA32[AR + mi * 16 + gid];
        r032[mi][1] = sqA32[AR + mi * 16 + gid + 8];
    }
    float half_mins0;
    {
        float v = sqA32[AR + lane];
#pragma unroll
        for (int o = 16; o; o >>= 1) v = fminf(v, __shfl_xor_sync(0xffffffffu, v, o));
        half_mins0 = 0.5f * v - 5.5f;
    }
    __syncthreads();   // mins1t visible

    // =========== phase 1 hot loop: 8 tiles, NO block barriers =====================
    for (int h = 0; h < 8; h++) {
        const int lc0 = h * 64 + wn2 * 32;            // block-local col base
        const int gcw = cg8 * 512 + lc0;              // global col base

        // b-fragments straight from global fp32 (coalesced LDG.64) + cvt
        uint32_t bf[2][4][2];
#pragma unroll
        for (int ni = 0; ni < 4; ni++) {
            const float* xc = x1 + (size_t)(gcw + ni * 8 + gid) * D;
            float2 p0 = *(const float2*)(xc + 2 * pid);
            float2 p1 = *(const float2*)(xc + 2 * pid + 8);
            float2 p2 = *(const float2*)(xc + 16 + 2 * pid);
            float2 p3 = *(const float2*)(xc + 16 + 2 * pid + 8);
            asm("cvt.rn.bf16x2.f32 %0, %1, %2;" : "=r"(bf[0][ni][0]) : "f"(p0.y), "f"(p0.x));
            asm("cvt.rn.bf16x2.f32 %0, %1, %2;" : "=r"(bf[0][ni][1]) : "f"(p1.y), "f"(p1.x));
            asm("cvt.rn.bf16x2.f32 %0, %1, %2;" : "=r"(bf[1][ni][0]) : "f"(p2.y), "f"(p2.x));
            asm("cvt.rn.bf16x2.f32 %0, %1, %2;" : "=r"(bf[1][ni][1]) : "f"(p3.y), "f"(p3.x));
        }

        float acc[2][4][4];
#pragma unroll
        for (int mi = 0; mi < 2; mi++)
#pragma unroll
            for (int ni = 0; ni < 4; ni++)
#pragma unroll
                for (int f = 0; f < 4; f++) acc[mi][ni][f] = 0.0f;
#pragma unroll
        for (int kk = 0; kk < 2; kk++)
#pragma unroll
            for (int mi = 0; mi < 2; mi++)
#pragma unroll
                for (int ni = 0; ni < 4; ni++)
                    HMMA(acc[mi][ni], afr[kk][mi][0], afr[kk][mi][1],
                         afr[kk][mi][2], afr[kk][mi][3], bf[kk][ni][0], bf[kk][ni][1]);

        // ---- cheap exact screen: max dot vs warp-min norms ----
        // no element has m<11 if 2*max(acc) <= min_s0 + min_s1 - 11
        float mx = acc[0][0][0];
#pragma unroll
        for (int mi = 0; mi < 2; mi++)
#pragma unroll
            for (int ni = 0; ni < 4; ni++)
#pragma unroll
                for (int f = 0; f < 4; f++) mx = fmaxf(mx, acc[mi][ni][f]);
        float thr = fmaf(0.5f, mins1t[h], half_mins0);
        unsigned fb = __ballot_sync(0xffffffffu, mx > thr);

        int anyb = 0;
        if (fb) {   // rare: exact per-element screen
            int need = 0;
#pragma unroll
            for (int ni = 0; ni < 4; ni++) {
                int lc = lc0 + ni * 8 + 2 * pid;
                float s1a = sq1c[lc], s1b = sq1c[lc + 1];
#pragma unroll
                for (int mi = 0; mi < 2; mi++) {
                    float m0 = fmaf(-2.0f, acc[mi][ni][0], r032[mi][0] + s1a);
                    float m1 = fmaf(-2.0f, acc[mi][ni][1], r032[mi][0] + s1b);
                    float m2 = fmaf(-2.0f, acc[mi][ni][2], r032[mi][1] + s1a);
                    float m3 = fmaf(-2.0f, acc[mi][ni][3], r032[mi][1] + s1b);
                    need |= (fminf(fminf(m0, m1), fminf(m2, m3)) < 11.0f) ? 1 : 0;
                }
            }
            anyb = __ballot_sync(0xffffffffu, need) ? 1 : 0;
        }
        if (lane == 0) flags[h * 8 + w] = anyb;   // unique slot per (h,w): no race
    }
    __syncthreads();           // all flags visible

    // -------- cold pass: complete flagged half-tiles exactly (rare) --------------
    {
        int blkany = 0;
        for (int h = 0; h < 8; h++) {
            int f = flags[h * 8 + 0] | flags[h * 8 + 1] | flags[h * 8 + 2] |
                    flags[h * 8 + 3] | flags[h * 8 + 4] | flags[h * 8 + 5] |
                    flags[h * 8 + 6] | flags[h * 8 + 7];
            if (tid == 0) g_map2[rs * NHT + cg8 * 8 + h] = f;
            blkany |= f;
            if (!f) continue;

            const int gc = cg8 * 512 + h * 64 + wn2 * 32;
            float s1f = 0.0f;
            {
                const float* xr = x1 + (size_t)(gc + lane) * D;
#pragma unroll
                for (int j = 0; j < 16; j++) {
                    float4 t = *(const float4*)(xr + j * 4);
                    s1f += t.x * t.x + t.y * t.y + t.z * t.z + t.w * t.w;
                }
            }
            float acc[2][4][4];
#pragma unroll
            for (int mi = 0; mi < 2; mi++)
#pragma unroll
                for (int ni = 0; ni < 4; ni++)
#pragma unroll
                    for (int ff = 0; ff < 4; ff++) acc[mi][ni][ff] = 0.0f;
#pragma unroll
            for (int ks = 0; ks < 4; ks++) {
                const int ac = ks * 8 + pid;
                uint32_t a[2][4], b[4][2];
#pragma unroll
                for (int mi = 0; mi < 2; mi++) {
                    int r = AR + mi * 16 + gid;
                    a[mi][0] = Ah[r * SA + ac];
                    a[mi][1] = Ah[(r + 8) * SA + ac];
                    a[mi][2] = Ah[r * SA + ac + 4];
                    a[mi][3] = Ah[(r + 8) * SA + ac + 4];
                }
#pragma unroll
                for (int ni = 0; ni < 4; ni++) {
                    const float* xc = x1 + (size_t)(gc + ni * 8 + gid) * D + ks * 16;
                    float2 f0 = *(const float2*)(xc + 2 * pid);
                    float2 f1 = *(const float2*)(xc + 2 * pid + 8);
                    asm("cvt.rn.bf16x2.f32 %0, %1, %2;" : "=r"(b[ni][0]) : "f"(f0.y), "f"(f0.x));
                    asm("cvt.rn.bf16x2.f32 %0, %1, %2;" : "=r"(b[ni][1]) : "f"(f1.y), "f"(f1.x));
                }
#pragma unroll
                for (int mi = 0; mi < 2; mi++)
#pragma unroll
                    for (int ni = 0; ni < 4; ni++)
                        HMMA(acc[mi][ni], a[mi][0], a[mi][1], a[mi][2], a[mi][3],
                             b[ni][0], b[ni][1]);
            }
#pragma unroll
            for (int mi = 0; mi < 2; mi++) {
                float s0a = sqA64[AR + mi * 16 + gid];
                float s0b = sqA64[AR + mi * 16 + gid + 8];
#pragma unroll
                for (int ni = 0; ni < 4; ni++) {
                    float s1a = __shfl_sync(0xffffffffu, s1f, ni * 8 + 2 * pid);
                    float s1b = __shfl_sync(0xffffffffu, s1f, ni * 8 + 2 * pid + 1);
                    int c = gc + ni * 8 + 2 * pid;
                    float m0 = fmaxf(fmaf(-2.0f, acc[mi][ni][0], s0a + s1a), 0.0f);
                    float m1 = fmaxf(fmaf(-2.0f, acc[mi][ni][1], s0a + s1b), 0.0f);
                    float m2 = fmaxf(fmaf(-2.0f, acc[mi][ni][2], s0b + s1a), 0.0f);
                    float m3 = fmaxf(fmaf(-2.0f, acc[mi][ni][3], s0b + s1b), 0.0f);
                    int r0 = gr + mi * 16 + gid;
                    *(float2*)(g_M + (size_t)r0 * N + c)       = make_float2(m0, m1);
                    *(float2*)(g_M + (size_t)(r0 + 8) * N + c) = make_float2(m2, m3);
                    *(float2*)(g_K + (size_t)r0 * N + c)       =
                        make_float2(expf(-10.0f * m0), expf(-10.0f * m1));
                    *(float2*)(g_K + (size_t)(r0 + 8) * N + c) =
                        make_float2(expf(-10.0f * m2), expf(-10.0f * m3));
                }
            }
        }
        if (tid == 0) g_blockany[bid] = blkany;
    }
    gsync();                   // the ONLY grid barrier on the zero fast path

    // =========== phase 2: Sinkhorn (or exact zero fast path) ======================
    {
        int loc = g_blockany[tid];            // NTHR == NB
        if (!__syncthreads_or(loc)) {
            if (bid == 0 && tid == 0) out[0] = 0.0f;   // P == 0 exactly
            return;                                     // uniform across blocks
        }
    }

    const float AB    = 1.0f / (float)N;
    const float DELTA = 1e-8f;
    {
        int gi = bid * NTHR + tid;
        if (gi < N) { g_u[gi] = 1.0f; g_v[gi] = 1.0f; }
    }
    gsync();

    for (int it = 0; it < ITERS; it++) {
        // u-pass: 16 rows/block, 2 rows/warp; skip all-zero half-tiles
#pragma unroll
        for (int rr = 0; rr < 2; rr++) {
            int r  = bid * 16 + w * 2 + rr;
            int rt = r >> 7;
            const int* map = g_map2 + rt * NHT;
            const float4* kr = (const float4*)(g_K + (size_t)r * N);
            const float4* vv = (const float4*)g_v;
            float s = 0.0f;
            for (int hct = 0; hct < NHT; hct++) {
                if (!map[hct]) continue;
                if (lane < 16) {
                    int j = hct * 16 + lane;
                    float4 kq = kr[j];
                    float4 vq = vv[j];
                    s += kq.x * vq.x + kq.y * vq.y + kq.z * vq.z + kq.w * vq.w;
                }
            }
#pragma unroll
            for (int o = 16; o; o >>= 1) s += __shfl_xor_sync(0xffffffffu, s, o);
            if (lane == 0) {
                float un = AB / (s + DELTA);
                if (un != g_u[r]) g_changed[it] = 1;
                g_u[r] = un;
            }
        }
        gsync();

        // v-pass: 16 cols/block; col = bid*16 + (tid>>4), 16-row stride
        {
            int cl  = tid >> 4;
            int ri  = tid & 15;
            int c   = bid * 16 + cl;
            int hct = bid >> 2;
            float s = 0.0f;
            for (int rt = 0; rt < NT; rt++) {
                if (!g_map2[rt * NHT + hct]) continue;
                int rbase = rt * 128;
#pragma unroll 8
                for (int r = rbase + ri; r < rbase + 128; r += 16)
                    s += g_K[(size_t)r * N + c] * g_u[r];
            }
            sred[tid] = s;
            __syncthreads();
            if (tid < 16) {
                float t = 0.0f;
#pragma unroll
                for (int g = 0; g < 16; g++) t += sred[tid * 16 + g];
                float vn = AB / (t + DELTA);
                int c2 = bid * 16 + tid;
                if (vn != g_v[c2]) g_changed[it] = 1;
                g_v[c2] = vn;
            }
        }
        gsync();

        if (g_changed[it] == 0) break;        // exact bitwise fixed point
    }

    // cost = sum_ij u_i * K_ij * v_j * M_ij (zero half-tiles contribute 0)
    {
        float wsum = 0.0f;
#pragma unroll
        for (int rr = 0; rr < 2; rr++) {
            int r  = bid * 16 + w * 2 + rr;
            int rt = r >> 7;
            const int* map = g_map2 + rt * NHT;
            const float4* kr = (const float4*)(g_K + (size_t)r * N);
            const float4* mr = (const float4*)(g_M + (size_t)r * N);
            const float4* vv = (const float4*)g_v;
            float s = 0.0f;
            for (int hct = 0; hct < NHT; hct++) {
                if (!map[hct]) continue;
                if (lane < 16) {
                    int j = hct * 16 + lane;
                    float4 kq = kr[j];
                    float4 mq = mr[j];
                    float4 vq = vv[j];
                    s += kq.x * mq.x * vq.x + kq.y * mq.y * vq.y
                       + kq.z * mq.z * vq.z + kq.w * mq.w * vq.w;
                }
            }
#pragma unroll
            for (int o = 16; o; o >>= 1) s += __shfl_xor_sync(0xffffffffu, s, o);
            if (lane == 0) wsum += s * g_u[r];
        }
        if (lane == 0) atomicAdd(&g_cost, wsum);
    }
    gsync();
    if (bid == 0 && tid == 0) out[0] = g_cost;
}

// ---------------- launch: ONE kernel ----------------------------------------------
extern "C" void kernel_launch(void* const* d_in, const int* in_sizes, int n_in,
                              void* d_out, int out_size) {
    const float* x0 = (const float*)d_in[0];
    const float* x1 = (const float*)d_in[1];
    float* out = (float*)d_out;
    kern_all<<<NB, NTHR>>>(x0, x1, out);
}

// round 17
// speedup vs baseline: 1.5118x; 1.5118x over previous
#include <cuda_runtime.h>
#include <cuda_bf16.h>
#include <cstdint>

#define N      4096
#define D      64
#define NB     256      // 2 persistent blocks per SM, all co-resident
#define NTHR   256      // 8 warps
#define ITERS  100
#define NT     32       // 32 row-slabs
#define NHT    64       // 64 column half-tiles (64 cols each)
#define SA     36       // A bf16 smem row stride (uint32)
#define SBH    20       // B bf16 half-tile row stride (uint32)

// ---------------- device globals (no allocation allowed) --------------------------
__device__ float    g_K[(size_t)N * N];   // written only for flagged half-tiles
__device__ float    g_M[(size_t)N * N];
__device__ float    g_u[N], g_v[N];
__device__ unsigned g_bar_count;
__device__ unsigned g_bar_phase;          // monotone across replays; compared relatively
__device__ int      g_changed[ITERS];
__device__ float    g_cost;
__device__ int      g_map2[NT * NHT];     // per 128x64 half-tile flag
__device__ int      g_blockany[NB];

// ---------------- grid barrier: arrivals atomic, polls are acquire LOADS -----------
__device__ __forceinline__ void gsync() {
    __syncthreads();
    if (threadIdx.x == 0) {
        __threadfence();
        unsigned ph = atomicAdd(&g_bar_phase, 0u);   // strong read BEFORE arrival
        if (atomicAdd(&g_bar_count, 1u) == (unsigned)NB - 1u) {
            atomicExch(&g_bar_count, 0u);
            atomicAdd(&g_bar_phase, 1u);             // release
        } else {
            unsigned cur;
            do {
                __nanosleep(64);
                asm volatile("ld.acquire.gpu.global.u32 %0, [%1];"
                             : "=r"(cur) : "l"(&g_bar_phase));
            } while (cur == ph);
        }
        __threadfence();
    }
    __syncthreads();
}

#define HMMA(accq, a0, a1, a2, a3, b0, b1)                                   \
    asm volatile(                                                            \
        "mma.sync.aligned.m16n8k16.row.col.f32.bf16.bf16.f32 "               \
        "{%0,%1,%2,%3}, {%4,%5,%6,%7}, {%8,%9}, {%0,%1,%2,%3};"              \
        : "+f"((accq)[0]), "+f"((accq)[1]), "+f"((accq)[2]), "+f"((accq)[3]) \
        : "r"(a0), "r"(a1), "r"(a2), "r"(a3), "r"(b0), "r"(b1))

// =============== the whole pipeline in ONE persistent kernel =======================
__global__ void __launch_bounds__(NTHR, 2) kern_all(const float* __restrict__ x0,
                                                    const float* __restrict__ x1,
                                                    float* __restrict__ out) {
    // u32 pool: Ah[4608] | Bb 2x1280 | sq1t 2x64 | sqA32[128] | sqA64[128] | flags[64]
    __shared__ uint32_t s_pool[7616];                // 30.5 KB
    uint32_t* const Ah    = s_pool;
    uint32_t* const Bb    = s_pool + 4608;           // 2 buffers x 1280
    float*    const sq1t  = (float*)(s_pool + 7168); // 2 x 64 (per-tile sq1, dims 0..31)
    float*    const sqA32 = (float*)(s_pool + 7296);
    float*    const sqA64 = (float*)(s_pool + 7424);
    int*      const flags = (int*)(s_pool + 7552);   // [tile][warp] 8x8
    float*    const sred  = (float*)s_pool;          // phase-2 overlay

    const int tid  = threadIdx.x;
    const int bid  = blockIdx.x;
    const int lane = tid & 31;
    const int w    = tid >> 5;                // 0..7
    const int gid  = lane >> 2;
    const int pid  = lane & 3;
    const int wm   = w >> 1;                  // 0..3 (32-row strips)
    const int wn2  = w & 1;                   // 0..1 (32-col strips in 64)

    if (bid == 0) {
        if (tid == 0) g_cost = 0.0f;
        if (tid < ITERS) g_changed[tid] = 0;
    }

    // =========== phase 1: local A conversion + reg-pipelined screened GEMM ========
    const int rs  = bid >> 3;                 // row slab 0..31
    const int cg8 = bid & 7;                  // column group: cols cg8*512..+512

    // -- B half-tile stage: LDG fp32 (dims 0..31) into regs --
    const int br1 = tid >> 3;                 // 0..31 (row within half of tile)
    const int bc4 = tid & 7;                  // float4 within 128B lo-half
    float4 breg[2];
    auto ldB = [&](int h) {
        const float* base = x1 + (size_t)(cg8 * 512 + h * 64) * D + bc4 * 4;
        breg[0] = *(const float4*)(base + (size_t)br1 * D);
        breg[1] = *(const float4*)(base + (size_t)(br1 + 32) * D);
    };
    // -- convert staged tile to bf16 smem + per-row sq1 (8-lane shfl tree) --
    auto stB = [&](int buf) {
        float sq0 = 0.0f, sq1v = 0.0f;
#pragma unroll
        for (int j = 0; j < 2; j++) {
            float4 v = breg[j];
            __nv_bfloat162 p0 = __floats2bfloat162_rn(v.x, v.y);
            __nv_bfloat162 p1 = __floats2bfloat162_rn(v.z, v.w);
            uint32_t* d = Bb + buf * 1280 + (br1 + j * 32) * SBH + bc4 * 2;
            d[0] = *(uint32_t*)&p0;
            d[1] = *(uint32_t*)&p1;
            float s = v.x * v.x + v.y * v.y + v.z * v.z + v.w * v.w;
            if (j == 0) sq0 = s; else sq1v = s;
        }
#pragma unroll
        for (int o = 1; o < 8; o <<= 1) {
            sq0  += __shfl_xor_sync(0xffffffffu, sq0,  o);
            sq1v += __shfl_xor_sync(0xffffffffu, sq1v, o);
        }
        if ((lane & 7) == 0) {
            sq1t[buf * 64 + br1]      = sq0;
            sq1t[buf * 64 + br1 + 32] = sq1v;
        }
    };

    ldB(0);                                   // tile-0 LDG in flight

    // -- A slab: fp32 -> bf16 smem + in-pass row norms --
    {
        const float* GA = x0 + (size_t)(rs * 128) * D;
#pragma unroll
        for (int i = 0; i < 8; i++) {
            int f = tid + i * NTHR;           // 0..2047
            int r = f >> 4; int q = f & 15;
            float4 v = *(const float4*)(GA + (size_t)r * D + q * 4);
            __nv_bfloat162 p0 = __floats2bfloat162_rn(v.x, v.y);
            __nv_bfloat162 p1 = __floats2bfloat162_rn(v.z, v.w);
            Ah[r * SA + q * 2]     = *(uint32_t*)&p0;
            Ah[r * SA + q * 2 + 1] = *(uint32_t*)&p1;
            float s = v.x * v.x + v.y * v.y + v.z * v.z + v.w * v.w;
            float s32 = (q < 8) ? s : 0.0f;
#pragma unroll
            for (int o = 1; o < 16; o <<= 1) {
                s   += __shfl_xor_sync(0xffffffffu, s,   o);
                s32 += __shfl_xor_sync(0xffffffffu, s32, o);
            }
            if ((lane & 15) == 0) { sqA32[r] = s32; sqA64[r] = s; }
        }
    }

    stB(0);
    __syncthreads();           // Ah + sq + buf0 visible

    // -- hoist A fragments (dims 0..31) + row norms: tile-invariant ----------------
    const int gr = rs * 128 + wm * 32;
    const int AR = wm * 32, BR = wn2 * 32;
    uint32_t afr[2][2][4];
#pragma unroll
    for (int kk = 0; kk < 2; kk++) {
        const int ac = kk * 8 + pid;
#pragma unroll
        for (int mi = 0; mi < 2; mi++) {
            int r = AR + mi * 16 + gid;
            afr[kk][mi][0] = Ah[r * SA + ac];
            afr[kk][mi][1] = Ah[(r + 8) * SA + ac];
            afr[kk][mi][2] = Ah[r * SA + ac + 4];
            afr[kk][mi][3] = Ah[(r + 8) * SA + ac + 4];
        }
    }
    float r032[2][2];
#pragma unroll
    for (int mi = 0; mi < 2; mi++) {
        r032[mi][0] = sqA32[AR + mi * 16 + gid];
        r032[mi][1] = sqA32[AR + mi * 16 + gid + 8];
    }

    int cur = 0;
    for (int h = 0; h < 8; h++) {
        if (h < 7) ldB(h + 1);                // LDG latency hides under mma + screen

        float acc[2][4][4];
#pragma unroll
        for (int mi = 0; mi < 2; mi++)
#pragma unroll
            for (int ni = 0; ni < 4; ni++)
#pragma unroll
                for (int f = 0; f < 4; f++) acc[mi][ni][f] = 0.0f;

        // mma dims 0..31: a from hoisted regs, b from smem
        const uint32_t* Bh = Bb + cur * 1280;
#pragma unroll
        for (int kk = 0; kk < 2; kk++) {
            const int bc = kk * 8 + pid;
            uint32_t b[4][2];
#pragma unroll
            for (int ni = 0; ni < 4; ni++) {
                int c = BR + ni * 8 + gid;
                b[ni][0] = Bh[c * SBH + bc];
                b[ni][1] = Bh[c * SBH + bc + 4];
            }
#pragma unroll
            for (int mi = 0; mi < 2; mi++)
#pragma unroll
                for (int ni = 0; ni < 4; ni++)
                    HMMA(acc[mi][ni], afr[kk][mi][0], afr[kk][mi][1],
                         afr[kk][mi][2], afr[kk][mi][3], b[ni][0], b[ni][1]);
        }

        // exact screen: partial M (dims 0..31) lower-bounds full M
        int need = 0;
#pragma unroll
        for (int ni = 0; ni < 4; ni++) {
            int lc = wn2 * 32 + ni * 8 + 2 * pid;
            float s1a = sq1t[cur * 64 + lc];
            float s1b = sq1t[cur * 64 + lc + 1];
#pragma unroll
            for (int mi = 0; mi < 2; mi++) {
                float m0 = fmaf(-2.0f, acc[mi][ni][0], r032[mi][0] + s1a);
                float m1 = fmaf(-2.0f, acc[mi][ni][1], r032[mi][0] + s1b);
                float m2 = fmaf(-2.0f, acc[mi][ni][2], r032[mi][1] + s1a);
                float m3 = fmaf(-2.0f, acc[mi][ni][3], r032[mi][1] + s1b);
                need |= (fminf(fminf(m0, m1), fminf(m2, m3)) < 11.0f) ? 1 : 0;
            }
        }
        int anyb = __ballot_sync(0xffffffffu, need) ? 1 : 0;
        if (lane == 0) flags[h * 8 + w] = anyb;

        if (h < 7) {
            stB(cur ^ 1);      // buffer cur^1 free since barrier of iter h-1
            __syncthreads();   // publish buf cur^1 (and flags ordering is per-slot)
        }
        cur ^= 1;
    }
    __syncthreads();           // all flags visible

    // -------- cold pass: complete flagged half-tiles exactly (rare) --------------
    {
        int blkany = 0;
        for (int h = 0; h < 8; h++) {
            int f = flags[h * 8 + 0] | flags[h * 8 + 1] | flags[h * 8 + 2] |
                    flags[h * 8 + 3] | flags[h * 8 + 4] | flags[h * 8 + 5] |
                    flags[h * 8 + 6] | flags[h * 8 + 7];
            if (tid == 0) g_map2[rs * NHT + cg8 * 8 + h] = f;
            blkany |= f;
            if (!f) continue;

            const int gc = cg8 * 512 + h * 64 + wn2 * 32;
            // per-lane full sq1_64 for col gc+lane (from global fp32)
            float s1f = 0.0f;
            {
                const float* xr = x1 + (size_t)(gc + lane) * D;
#pragma unroll
                for (int j = 0; j < 16; j++) {
                    float4 t = *(const float4*)(xr + j * 4);
                    s1f += t.x * t.x + t.y * t.y + t.z * t.z + t.w * t.w;
                }
            }
            float acc[2][4][4];
#pragma unroll
            for (int mi = 0; mi < 2; mi++)
#pragma unroll
                for (int ni = 0; ni < 4; ni++)
#pragma unroll
                    for (int ff = 0; ff < 4; ff++) acc[mi][ni][ff] = 0.0f;
            // full 64-dim mma: a from bf16 smem, b cvt from global fp32
#pragma unroll
            for (int ks = 0; ks < 4; ks++) {
                const int ac = ks * 8 + pid;
                uint32_t a[2][4], b[4][2];
#pragma unroll
                for (int mi = 0; mi < 2; mi++) {
                    int r = AR + mi * 16 + gid;
                    a[mi][0] = Ah[r * SA + ac];
                    a[mi][1] = Ah[(r + 8) * SA + ac];
                    a[mi][2] = Ah[r * SA + ac + 4];
                    a[mi][3] = Ah[(r + 8) * SA + ac + 4];
                }
#pragma unroll
                for (int ni = 0; ni < 4; ni++) {
                    const float* xc = x1 + (size_t)(gc + ni * 8 + gid) * D + ks * 16;
                    float2 f0 = *(const float2*)(xc + 2 * pid);
                    float2 f1 = *(const float2*)(xc + 2 * pid + 8);
                    asm("cvt.rn.bf16x2.f32 %0, %1, %2;" : "=r"(b[ni][0]) : "f"(f0.y), "f"(f0.x));
                    asm("cvt.rn.bf16x2.f32 %0, %1, %2;" : "=r"(b[ni][1]) : "f"(f1.y), "f"(f1.x));
                }
#pragma unroll
                for (int mi = 0; mi < 2; mi++)
#pragma unroll
                    for (int ni = 0; ni < 4; ni++)
                        HMMA(acc[mi][ni], a[mi][0], a[mi][1], a[mi][2], a[mi][3],
                             b[ni][0], b[ni][1]);
            }
#pragma unroll
            for (int mi = 0; mi < 2; mi++) {
                float s0a = sqA64[AR + mi * 16 + gid];
                float s0b = sqA64[AR + mi * 16 + gid + 8];
#pragma unroll
                for (int ni = 0; ni < 4; ni++) {
                    float s1a = __shfl_sync(0xffffffffu, s1f, ni * 8 + 2 * pid);
                    float s1b = __shfl_sync(0xffffffffu, s1f, ni * 8 + 2 * pid + 1);
                    int c = gc + ni * 8 + 2 * pid;
                    float m0 = fmaxf(fmaf(-2.0f, acc[mi][ni][0], s0a + s1a), 0.0f);
                    float m1 = fmaxf(fmaf(-2.0f, acc[mi][ni][1], s0a + s1b), 0.0f);
                    float m2 = fmaxf(fmaf(-2.0f, acc[mi][ni][2], s0b + s1a), 0.0f);
                    float m3 = fmaxf(fmaf(-2.0f, acc[mi][ni][3], s0b + s1b), 0.0f);
                    int r0 = gr + mi * 16 + gid;
                    *(float2*)(g_M + (size_t)r0 * N + c)       = make_float2(m0, m1);
                    *(float2*)(g_M + (size_t)(r0 + 8) * N + c) = make_float2(m2, m3);
                    *(float2*)(g_K + (size_t)r0 * N + c)       =
                        make_float2(expf(-10.0f * m0), expf(-10.0f * m1));
                    *(float2*)(g_K + (size_t)(r0 + 8) * N + c) =
                        make_float2(expf(-10.0f * m2), expf(-10.0f * m3));
                }
            }
        }
        if (tid == 0) g_blockany[bid] = blkany;
    }
    gsync();                   // the ONLY grid barrier on the zero fast path

    // =========== phase 2: Sinkhorn (or exact zero fast path) ======================
    {
        int loc = g_blockany[tid];            // NTHR == NB
        if (!__syncthreads_or(loc)) {
            if (bid == 0 && tid == 0) out[0] = 0.0f;   // P == 0 exactly
            return;                                     // uniform across blocks
        }
    }

    const float AB    = 1.0f / (float)N;
    const float DELTA = 1e-8f;
    {
        int gi = bid * NTHR + tid;
        if (gi < N) { g_u[gi] = 1.0f; g_v[gi] = 1.0f; }
    }
    gsync();

    for (int it = 0; it < ITERS; it++) {
        // u-pass: 16 rows/block, 2 rows/warp; skip all-zero half-tiles
#pragma unroll
        for (int rr = 0; rr < 2; rr++) {
            int r  = bid * 16 + w * 2 + rr;
            int rt = r >> 7;
            const int* map = g_map2 + rt * NHT;
            const float4* kr = (const float4*)(g_K + (size_t)r * N);
            const float4* vv = (const float4*)g_v;
            float s = 0.0f;
            for (int hct = 0; hct < NHT; hct++) {
                if (!map[hct]) continue;
                if (lane < 16) {
                    int j = hct * 16 + lane;
                    float4 kq = kr[j];
                    float4 vq = vv[j];
                    s += kq.x * vq.x + kq.y * vq.y + kq.z * vq.z + kq.w * vq.w;
                }
            }
#pragma unroll
            for (int o = 16; o; o >>= 1) s += __shfl_xor_sync(0xffffffffu, s, o);
            if (lane == 0) {
                float un = AB / (s + DELTA);
                if (un != g_u[r]) g_changed[it] = 1;
                g_u[r] = un;
            }
        }
        gsync();

        // v-pass: 16 cols/block; col = bid*16 + (tid>>4), 16-row stride
        {
            int cl  = tid >> 4;
            int ri  = tid & 15;
            int c   = bid * 16 + cl;
            int hct = bid >> 2;
            float s = 0.0f;
            for (int rt = 0; rt < NT; rt++) {
                if (!g_map2[rt * NHT + hct]) continue;
                int rbase = rt * 128;
#pragma unroll 8
                for (int r = rbase + ri; r < rbase + 128; r += 16)
                    s += g_K[(size_t)r * N + c] * g_u[r];
            }
            sred[tid] = s;
            __syncthreads();
            if (tid < 16) {
                float t = 0.0f;
#pragma unroll
                for (int g = 0; g < 16; g++) t += sred[tid * 16 + g];
                float vn = AB / (t + DELTA);
                int c2 = bid * 16 + tid;
                if (vn != g_v[c2]) g_changed[it] = 1;
                g_v[c2] = vn;
            }
        }
        gsync();

        if (g_changed[it] == 0) break;        // exact bitwise fixed point
    }

    // cost = sum_ij u_i * K_ij * v_j * M_ij (zero half-tiles contribute 0)
    {
        float wsum = 0.0f;
#pragma unroll
        for (int rr = 0; rr < 2; rr++) {
            int r  = bid * 16 + w * 2 + rr;
            int rt = r >> 7;
            const int* map = g_map2 + rt * NHT;
            const float4* kr = (const float4*)(g_K + (size_t)r * N);
            const float4* mr = (const float4*)(g_M + (size_t)r * N);
            const float4* vv = (const float4*)g_v;
            float s = 0.0f;
            for (int hct = 0; hct < NHT; hct++) {
                if (!map[hct]) continue;
                if (lane < 16) {
                    int j = hct * 16 + lane;
                    float4 kq = kr[j];
                    float4 mq = mr[j];
                    float4 vq = vv[j];
                    s += kq.x * mq.x * vq.x + kq.y * mq.y * vq.y
                       + kq.z * mq.z * vq.z + kq.w * mq.w * vq.w;
                }
            }
#pragma unroll
            for (int o = 16; o; o >>= 1) s += __shfl_xor_sync(0xffffffffu, s, o);
            if (lane == 0) wsum += s * g_u[r];
        }
        if (lane == 0) atomicAdd(&g_cost, wsum);
    }
    gsync();
    if (bid == 0 && tid == 0) out[0] = g_cost;
}

// ---------------- launch: ONE kernel ----------------------------------------------
extern "C" void kernel_launch(void* const* d_in, const int* in_sizes, int n_in,
                              void* d_out, int out_size) {
    const float* x0 = (const float*)d_in[0];
    const float* x1 = (const float*)d_in[1];
    float* out = (float*)d_out;
    kern_all<<<NB, NTHR>>>(x0, x1, out);
}